// round 3
// baseline (speedup 1.0000x reference)
#include <cuda_runtime.h>
#include <math.h>
#include <math_constants.h>

// Problem constants (shapes fixed by setup_inputs)
#define B 16
#define C 1024
#define D 768
#define KH 306          // int((C-1) * 0.3)
#define KR 717          // (C-1) - KH
#define TAUF 0.1f
#define G 4             // anchors per block in main kernel

// ---- device scratch (no allocations allowed) ----
__device__ float          g_pT[D * C];        // normalized protos, transposed [k][j], 3 MB
__device__ float          g_loss[B * C];      // per-anchor loss (0 for non-positive)
__device__ unsigned char  g_randmem[B * C];   // per-b random-negative membership
__device__ float          g_poscnt[B];        // clip(pos count, 1)
__device__ int            g_list[B * C];      // compacted positive anchor indices
__device__ int            g_npos;
__device__ int            g_tstride;          // 1 = targets int32, 2 = targets int64

// ---------------------------------------------------------------------------
__global__ void k_init() {
    int i = blockIdx.x * blockDim.x + threadIdx.x;
    if (i < B * C) g_loss[i] = 0.f;
    if (i == 0) { g_npos = 0; g_tstride = 2; }
}

// Probe targets dtype: values are 0/1. If int64 (little-endian), all odd 32-bit
// words in the first B*C words are high-halves == 0. If int32, ~5% of odd words
// are nonzero. Only touches the first B*C words (safe for either dtype).
__global__ void k_detect(const int* __restrict__ tgw) {
    int i = blockIdx.x * blockDim.x + threadIdx.x;  // 0 .. B*C/2-1
    if (i < B * C / 2 && tgw[2 * i + 1] != 0) atomicExch(&g_tstride, 1);
}

// Normalize label_proto rows and write transposed: g_pT[k*C + j]
__global__ void k_pnorm(const float* __restrict__ p) {
    int j = blockIdx.x;          // proto row
    int tid = threadIdx.x;       // 256 threads
    __shared__ float red[256];
    float v0 = p[j * D + tid];
    float v1 = p[j * D + tid + 256];
    float v2 = p[j * D + tid + 512];
    red[tid] = v0 * v0 + v1 * v1 + v2 * v2;
    __syncthreads();
    for (int s = 128; s > 0; s >>= 1) {
        if (tid < s) red[tid] += red[tid + s];
        __syncthreads();
    }
    float inv = 1.f / fmaxf(sqrtf(red[0]), 1e-12f);
    g_pT[(tid      ) * C + j] = v0 * inv;
    g_pT[(tid + 256) * C + j] = v1 * inv;
    g_pT[(tid + 512) * C + j] = v2 * inv;
}

// Per batch element: pos count + random-negative set (top-KR of rand scores
// over negative columns, stable lowest-index tie-break like jax.lax.top_k).
__global__ void k_rand(const int* __restrict__ tg,
                       const float* __restrict__ rs) {
    int b = blockIdx.x;
    int tid = threadIdx.x;  // 1024 threads
    __shared__ unsigned long long keys[C];
    __shared__ int icnt[C];
    int ts = g_tstride;

    bool pos = (tg[(b * C + tid) * ts] != 0);
    g_randmem[b * C + tid] = 0;
    unsigned int vb = __float_as_uint(rs[b * C + tid]);  // uniform in [0,1): bits monotone
    keys[tid] = pos ? 0ull
                    : ((((unsigned long long)vb) << 32) |
                       (unsigned long long)(0xFFFFFFFFu - (unsigned)tid));
    icnt[tid] = pos ? 1 : 0;
    __syncthreads();

    for (int s = 512; s > 0; s >>= 1) {
        if (tid < s) icnt[tid] += icnt[tid + s];
        __syncthreads();
    }
    if (tid == 0) g_poscnt[b] = (float)(icnt[0] > 0 ? icnt[0] : 1);

    // bitonic sort descending (1024 elems, 1024 threads)
    for (int k = 2; k <= C; k <<= 1) {
        for (int st = k >> 1; st > 0; st >>= 1) {
            __syncthreads();
            int l = tid ^ st;
            if (l > tid) {
                unsigned long long a = keys[tid], bb = keys[l];
                bool up = (tid & k) != 0;
                bool sw = up ? (a > bb) : (a < bb);
                if (sw) { keys[tid] = bb; keys[l] = a; }
            }
        }
    }
    __syncthreads();
    if (tid < KR) {
        unsigned long long kk = keys[tid];
        if (kk != 0ull) {   // guard: never decode an empty slot
            unsigned int j = 0xFFFFFFFFu - (unsigned int)(kk & 0xFFFFFFFFull);
            if (j < C) g_randmem[b * C + j] = 1;
        }
    }
}

__global__ void k_compact(const int* __restrict__ tg) {
    int i = blockIdx.x * blockDim.x + threadIdx.x;
    int ts = g_tstride;
    if (i < B * C && tg[i * ts] != 0) {
        int p = atomicAdd(&g_npos, 1);
        g_list[p] = i;
    }
}

// Main: G positive anchors per block. SMEM-staged normalized f rows,
// coalesced float4 stream over transposed p, per-anchor bitonic top-KH.
__global__ void __launch_bounds__(256) k_main(const float* __restrict__ f,
                                              const int* __restrict__ tg) {
    __shared__ float f_s[G][D];
    __shared__ float sims[G][C];
    __shared__ float sortbuf[C];
    __shared__ float red[256];
    __shared__ int anchors[G];

    int tid = threadIdx.x;
    int npos = g_npos;
    int ts = g_tstride;
    int base = blockIdx.x * G;
    if (base >= npos) return;   // uniform exit

    if (tid < G) anchors[tid] = (base + tid < npos) ? g_list[base + tid] : -1;
    __syncthreads();

    // Load + normalize f rows (scaled by 1/(norm*TAU) so sims come out tempered)
    for (int u = 0; u < G; u++) {
        int a = anchors[u];
        float v0 = 0.f, v1 = 0.f, v2 = 0.f;
        if (a >= 0) {
            const float* fr = f + (size_t)a * D;
            v0 = fr[tid]; v1 = fr[tid + 256]; v2 = fr[tid + 512];
        }
        red[tid] = v0 * v0 + v1 * v1 + v2 * v2;
        __syncthreads();
        for (int s = 128; s > 0; s >>= 1) {
            if (tid < s) red[tid] += red[tid + s];
            __syncthreads();
        }
        float inv = (1.f / fmaxf(sqrtf(red[0]), 1e-12f)) * (1.f / TAUF);
        f_s[u][tid]       = v0 * inv;
        f_s[u][tid + 256] = v1 * inv;
        f_s[u][tid + 512] = v2 * inv;
        __syncthreads();
    }

    // GEMM: each thread owns 4 consecutive columns (float4), all G anchors
    float4 acc[G];
#pragma unroll
    for (int u = 0; u < G; u++) acc[u] = make_float4(0.f, 0.f, 0.f, 0.f);

    const float4* pT4 = reinterpret_cast<const float4*>(g_pT);
#pragma unroll 4
    for (int k = 0; k < D; k++) {
        float4 pv = pT4[k * (C / 4) + tid];
#pragma unroll
        for (int u = 0; u < G; u++) {
            float fv = f_s[u][k];
            acc[u].x += fv * pv.x;
            acc[u].y += fv * pv.y;
            acc[u].z += fv * pv.z;
            acc[u].w += fv * pv.w;
        }
    }
#pragma unroll
    for (int u = 0; u < G; u++) {
        sims[u][4 * tid + 0] = acc[u].x;
        sims[u][4 * tid + 1] = acc[u].y;
        sims[u][4 * tid + 2] = acc[u].z;
        sims[u][4 * tid + 3] = acc[u].w;
    }
    __syncthreads();

    // Per-anchor: hard top-KH over negative columns + random set LSE
    for (int u = 0; u < G; u++) {
        int a = anchors[u];
        if (a < 0) continue;   // uniform across block
        int b = a >> 10;
        int c = a & (C - 1);

        for (int j = tid; j < C; j += 256)
            sortbuf[j] = (tg[(b * C + j) * ts] == 0) ? sims[u][j] : -CUDART_INF_F;

        // bitonic sort descending, 256 threads over 1024 elems
        for (int k2 = 2; k2 <= C; k2 <<= 1) {
            for (int st = k2 >> 1; st > 0; st >>= 1) {
                __syncthreads();
                for (int i = tid; i < C; i += 256) {
                    int l = i ^ st;
                    if (l > i) {
                        float x = sortbuf[i], y = sortbuf[l];
                        bool up = (i & k2) != 0;
                        bool sw = up ? (x > y) : (x < y);
                        if (sw) { sortbuf[i] = y; sortbuf[l] = x; }
                    }
                }
            }
        }
        __syncthreads();

        float m = sortbuf[0];   // max over negatives (>= any rand-set sim)
        float spart = 0.f;
        for (int i = tid; i < KH; i += 256) spart += expf(sortbuf[i] - m);
        for (int j = tid; j < C; j += 256)
            if (g_randmem[b * C + j]) spart += expf(sims[u][j] - m);
        red[tid] = spart;
        __syncthreads();
        for (int s = 128; s > 0; s >>= 1) {
            if (tid < s) red[tid] += red[tid + s];
            __syncthreads();
        }
        if (tid == 0) {
            float lse = m + logf(red[0]);
            float ps = sims[u][c];
            float x = lse - ps;
            // softplus(x) = -log_prob
            float loss = fmaxf(x, 0.f) + log1pf(expf(-fabsf(x)));
            g_loss[a] = loss;
        }
        __syncthreads();
    }
}

// Deterministic final reduction: fixed-order strided sums + tree.
__global__ void k_final(float* __restrict__ out) {
    __shared__ float red[256];
    __shared__ float acc_s;
    int tid = threadIdx.x;
    if (tid == 0) acc_s = 0.f;
    __syncthreads();
    for (int b = 0; b < B; b++) {
        float p = 0.f;
        for (int c = tid; c < C; c += 256) p += g_loss[b * C + c];
        red[tid] = p;
        __syncthreads();
        for (int s = 128; s > 0; s >>= 1) {
            if (tid < s) red[tid] += red[tid + s];
            __syncthreads();
        }
        if (tid == 0) acc_s += red[0] / g_poscnt[b];
        __syncthreads();
    }
    if (tid == 0) out[0] = acc_s / (float)B;
}

// ---------------------------------------------------------------------------
extern "C" void kernel_launch(void* const* d_in, const int* in_sizes, int n_in,
                              void* d_out, int out_size) {
    const float* f  = (const float*)d_in[0];      // (B,C,D) fp32
    const float* p  = (const float*)d_in[1];      // (C,D)   fp32
    const int*   tg = (const int*)d_in[2];        // (B,C)   int32 or int64 (probed)
    const float* rs = (const float*)d_in[3];      // (B,C)   fp32
    float* out = (float*)d_out;

    k_init<<<(B * C + 1023) / 1024, 1024>>>();
    k_detect<<<(B * C / 2 + 255) / 256, 256>>>(tg);
    k_pnorm<<<C, 256>>>(p);
    k_rand<<<B, 1024>>>(tg, rs);
    k_compact<<<(B * C) / 256, 256>>>(tg);
    k_main<<<(B * C + G - 1) / G, 256>>>(f, tg);
    k_final<<<1, 256>>>(out);
}

// round 8
// speedup vs baseline: 1.7661x; 1.7661x over previous
#include <cuda_runtime.h>
#include <math.h>
#include <math_constants.h>

// Problem constants (shapes fixed by setup_inputs)
#define B 16
#define C 1024
#define D 768
#define KH 306          // int((C-1) * 0.3)
#define KR 717          // (C-1) - KH
#define TAUF 0.1f
#define GG 6            // anchors per GEMM group
#define GEMM_BLOCKS 304
#define SEL_BLOCKS 304

// ---- device scratch (module globals; no runtime allocation) ----
__device__ float          g_pT[D * C];            // normalized protos, transposed [k][c]
__device__ float          g_sims[B * C * C];      // sims rows by list position (worst case)
__device__ float          g_loss[B * C];
__device__ unsigned char  g_randmem[B * C];
__device__ float          g_poscnt[B];
__device__ int            g_list[B * C];
__device__ int            g_npos;
__device__ int            g_tstride;              // 1 = int32 targets, 2 = int64

// ===========================================================================
// setup: zero g_loss; single block probes targets dtype + zeroes g_npos.
// int64 0/1 values have all-zero odd (high) words; int32 targets have ~5%
// nonzero odd words -> ts=1.
__global__ void k_setup(const int* __restrict__ tgw) {
    int tid = threadIdx.x;
    int blk = blockIdx.x;
    if (blk < 16) {
        g_loss[blk * 1024 + tid] = 0.f;
    } else {
        __shared__ int flag;
        if (tid == 0) flag = 0;
        __syncthreads();
        bool nz = false;
#pragma unroll
        for (int k = 0; k < 8; k++) nz |= (tgw[2 * (tid + k * 1024) + 1] != 0);
        if (nz) flag = 1;
        __syncthreads();
        if (tid == 0) { g_tstride = flag ? 1 : 2; g_npos = 0; }
    }
}

// ===========================================================================
// Radix-select helper: finds the Ksel-th largest among per-thread 32-bit keys
// (key==0 means "excluded"). On exit: *sh_prefix = threshold key T,
// *sh_rem = number of elements equal to T that belong to the top-Ksel.
// Requires 1024 threads; all must call (keys may be 0).
__device__ __forceinline__ void radix_select_desc(
    unsigned key, int Ksel,
    unsigned* hist /*256*/, unsigned* S /*256*/, unsigned* wtot /*>=8*/,
    unsigned* sh_prefix, unsigned* sh_rem,
    int tid, int lane)
{
    if (tid == 0) { *sh_prefix = 0u; *sh_rem = (unsigned)Ksel; }
    __syncthreads();
#pragma unroll
    for (int byte = 3; byte >= 0; byte--) {
        int shift = byte * 8;
        if (tid < 256) hist[tid] = 0u;
        __syncthreads();
        unsigned pfx = *sh_prefix;
        bool match = (byte == 3) || ((key >> (shift + 8)) == (pfx >> (shift + 8)));
        if (match && key != 0u) atomicAdd(&hist[(key >> shift) & 255u], 1u);
        __syncthreads();
        if (tid < 256) {
            unsigned v = hist[tid];
#pragma unroll
            for (int d = 1; d < 32; d <<= 1) {          // warp suffix scan
                unsigned t2 = __shfl_down_sync(0xFFFFFFFFu, v, d);
                if (lane + d < 32) v += t2;
            }
            S[tid] = v;
            if (lane == 0) wtot[tid >> 5] = v;          // warp total (suffix @lane0)
        }
        __syncthreads();
        unsigned remloc = *sh_rem;                      // snapshot before writer phase
        if (tid < 256) {
            unsigned ws = 0;
            for (int w = (tid >> 5) + 1; w < 8; w++) ws += wtot[w];
            S[tid] += ws;                               // global suffix sums
        }
        __syncthreads();
        if (tid < 256) {
            unsigned st = S[tid];
            unsigned snext = (tid == 255) ? 0u : S[tid + 1];
            if (st >= remloc && snext < remloc) {
                *sh_prefix = pfx | ((unsigned)tid << shift);
                *sh_rem = remloc - snext;
            }
        }
        __syncthreads();
    }
}

// ===========================================================================
// prep: blocks 0..1023 = proto normalize+transpose; 1024..1039 = rand-negative
// set per batch elem (radix select, stable lowest-index tie-break); 1040..1055
// = compact positive anchors.
__global__ void __launch_bounds__(1024) k_prep(const float* __restrict__ p,
                                               const int* __restrict__ tg,
                                               const float* __restrict__ rs) {
    __shared__ unsigned hist[256];
    __shared__ unsigned S[256];
    __shared__ unsigned wtot[32];
    __shared__ unsigned sh_prefix, sh_rem;
    __shared__ float f_red[32];
    __shared__ float sh_inv;

    int tid = threadIdx.x;
    int lane = tid & 31, wid = tid >> 5;
    int blk = blockIdx.x;

    if (blk < 1024) {
        // ---- proto normalize row j = blk, write transposed ----
        int j = blk;
        float v = (tid < D) ? p[j * D + tid] : 0.f;
        float ss = v * v;
#pragma unroll
        for (int d = 16; d > 0; d >>= 1) ss += __shfl_xor_sync(0xFFFFFFFFu, ss, d);
        if (lane == 0) f_red[wid] = ss;
        __syncthreads();
        if (tid == 0) {
            float t = 0.f;
            for (int w = 0; w < 32; w++) t += f_red[w];
            sh_inv = 1.f / fmaxf(sqrtf(t), 1e-12f);
        }
        __syncthreads();
        if (tid < D) g_pT[tid * C + j] = v * sh_inv;
    } else if (blk < 1040) {
        // ---- rand-negative membership for batch b ----
        int b = blk - 1024;
        int ts = g_tstride;
        bool posc = (tg[(b * C + tid) * ts] != 0);
        float r = rs[b * C + tid];
        unsigned key = posc ? 0u : (__float_as_uint(r) + 1u);  // monotone, >0

        // positive count
        unsigned bal = __ballot_sync(0xFFFFFFFFu, posc);
        if (lane == 0) wtot[wid] = (unsigned)__popc(bal);
        __syncthreads();
        if (tid == 0) {
            unsigned cnt = 0;
            for (int w = 0; w < 32; w++) cnt += wtot[w];
            g_poscnt[b] = (float)(cnt > 0 ? cnt : 1u);
        }
        __syncthreads();

        radix_select_desc(key, KR, hist, S, wtot, &sh_prefix, &sh_rem, tid, lane);
        unsigned T = sh_prefix;
        unsigned remf = sh_rem;

        // tie resolution by lowest index (matches jax.lax.top_k stability)
        bool eq = (key == T);
        unsigned eb = __ballot_sync(0xFFFFFFFFu, eq);
        if (lane == 0) wtot[wid] = (unsigned)__popc(eb);
        __syncthreads();
        unsigned off = 0;
        for (int w = 0; w < wid; w++) off += wtot[w];
        unsigned rank = off + (unsigned)__popc(eb & ((1u << lane) - 1u));
        bool in = (key > T) || (eq && rank < remf);
        g_randmem[b * C + tid] = in ? (unsigned char)1 : (unsigned char)0;
    } else {
        // ---- compact positive anchors for batch b ----
        int b = blk - 1040;
        int ts = g_tstride;
        int a = b * C + tid;
        if (tg[a * ts] != 0) {
            int pidx = atomicAdd(&g_npos, 1);
            g_list[pidx] = a;
        }
    }
}

// ===========================================================================
// GEMM: persistent blocks over items = (anchor group of GG) x (column half).
// 256 threads, 2 cols/thread (float2), GG anchors -> 24 FFMA per 2 k-steps.
__global__ void __launch_bounds__(256) k_gemm(const float* __restrict__ f) {
    __shared__ float f_s[GG][D];
    __shared__ int s_anchor[GG];

    int tid = threadIdx.x;
    int wid = tid >> 5, lane = tid & 31;
    int npos = g_npos;
    int ng = (npos + GG - 1) / GG;
    int nitems = ng * 2;

    for (int item = blockIdx.x; item < nitems; item += GEMM_BLOCKS) {
        int grp = item >> 1;
        int half = item & 1;
        if (tid < GG) {
            int idx = grp * GG + tid;
            s_anchor[tid] = (idx < npos) ? g_list[idx] : -1;
        }
        __syncthreads();
        // warp w normalizes anchor w's feature row (scaled by 1/(norm*TAU))
        if (wid < GG) {
            int a = s_anchor[wid];
            float vs[24];
            float ss = 0.f;
            if (a >= 0) {
                const float* fr = f + (size_t)a * D;
#pragma unroll
                for (int t = 0; t < 24; t++) {
                    float v = fr[lane + 32 * t];
                    vs[t] = v; ss += v * v;
                }
            } else {
#pragma unroll
                for (int t = 0; t < 24; t++) vs[t] = 0.f;
            }
#pragma unroll
            for (int d = 16; d > 0; d >>= 1) ss += __shfl_xor_sync(0xFFFFFFFFu, ss, d);
            float inv = (1.f / fmaxf(sqrtf(ss), 1e-12f)) * (1.f / TAUF);
#pragma unroll
            for (int t = 0; t < 24; t++) f_s[wid][lane + 32 * t] = vs[t] * inv;
        }
        __syncthreads();

        int col = half * 512 + 2 * tid;
        const float* pc = g_pT + col;
        float acc[GG][2];
#pragma unroll
        for (int u = 0; u < GG; u++) { acc[u][0] = 0.f; acc[u][1] = 0.f; }

#pragma unroll 4
        for (int k = 0; k < D; k += 2) {
            float2 p0 = *(const float2*)(pc + (size_t)k * C);
            float2 p1 = *(const float2*)(pc + (size_t)(k + 1) * C);
#pragma unroll
            for (int u = 0; u < GG; u++) {
                float2 fv = *(const float2*)&f_s[u][k];
                acc[u][0] += fv.x * p0.x + fv.y * p1.x;
                acc[u][1] += fv.x * p0.y + fv.y * p1.y;
            }
        }
        int base = grp * GG;
#pragma unroll
        for (int u = 0; u < GG; u++) {
            if (base + u < npos) {
                float2 o; o.x = acc[u][0]; o.y = acc[u][1];
                *(float2*)&g_sims[(size_t)(base + u) * C + col] = o;
            }
        }
        __syncthreads();
    }
}

// ===========================================================================
// select+loss: one item per anchor, 1024 threads (one column each).
// Hard top-KH via radix select with exact tie handling (equal values give
// equal exp contributions); rand set via membership flags; stable softplus.
__global__ void __launch_bounds__(1024) k_select(const int* __restrict__ tg) {
    __shared__ unsigned hist[256];
    __shared__ unsigned S[256];
    __shared__ unsigned wtot[32];
    __shared__ unsigned sh_prefix, sh_rem;
    __shared__ unsigned u_red[32];
    __shared__ float f_red[32];
    __shared__ float s_vT, s_possim;

    int tid = threadIdx.x;
    int lane = tid & 31, wid = tid >> 5;
    int npos = g_npos;
    int ts = g_tstride;

    for (int i = blockIdx.x; i < npos; i += SEL_BLOCKS) {
        int a = g_list[i];
        int b = a >> 10;
        int c = a & (C - 1);

        float sim = g_sims[(size_t)i * C + tid];
        bool posc = (tg[(b * C + tid) * ts] != 0);
        unsigned bits = __float_as_uint(sim);
        unsigned key = posc ? 0u
                            : (bits ^ ((bits & 0x80000000u) ? 0xFFFFFFFFu : 0x80000000u));
        if (tid == c) s_possim = sim;

        // max negative sim (= top-1 hard, hence max of the whole selected union)
        unsigned mk = key;
#pragma unroll
        for (int d = 16; d > 0; d >>= 1) mk = max(mk, __shfl_xor_sync(0xFFFFFFFFu, mk, d));
        if (lane == 0) u_red[wid] = mk;
        __syncthreads();
        if (tid < 32) {
            unsigned t = u_red[tid];
#pragma unroll
            for (int d = 16; d > 0; d >>= 1) t = max(t, __shfl_xor_sync(0xFFFFFFFFu, t, d));
            if (tid == 0) u_red[0] = t;
        }
        __syncthreads();
        unsigned maxkey = u_red[0];
        unsigned mbits = (maxkey & 0x80000000u) ? (maxkey ^ 0x80000000u) : ~maxkey;
        float m = __uint_as_float(mbits);

        radix_select_desc(key, KH, hist, S, wtot, &sh_prefix, &sh_rem, tid, lane);
        unsigned T = sh_prefix;
        unsigned remf = sh_rem;

        float contrib = 0.f;
        if (key > T) contrib = expf(sim - m);
        if (key == T) s_vT = sim;                 // benign: all writers equal
        if (g_randmem[b * C + tid]) contrib += expf(sim - m);
        __syncthreads();

        // block reduce contrib
#pragma unroll
        for (int d = 16; d > 0; d >>= 1) contrib += __shfl_xor_sync(0xFFFFFFFFu, contrib, d);
        if (lane == 0) f_red[wid] = contrib;
        __syncthreads();
        if (tid == 0) {
            float tot = 0.f;
            for (int w = 0; w < 32; w++) tot += f_red[w];
            tot += (float)remf * expf(s_vT - m);
            float lse = m + logf(tot);
            float x = lse - s_possim;
            g_loss[a] = fmaxf(x, 0.f) + log1pf(expf(-fabsf(x)));
        }
        __syncthreads();
    }
}

// ===========================================================================
// final: deterministic fixed-order reduction to the scalar loss.
__global__ void k_final(float* __restrict__ out) {
    __shared__ float red[256];
    __shared__ float acc_s;
    int tid = threadIdx.x;
    if (tid == 0) acc_s = 0.f;
    __syncthreads();
    for (int b = 0; b < B; b++) {
        float p = 0.f;
        for (int c = tid; c < C; c += 256) p += g_loss[b * C + c];
        red[tid] = p;
        __syncthreads();
        for (int s = 128; s > 0; s >>= 1) {
            if (tid < s) red[tid] += red[tid + s];
            __syncthreads();
        }
        if (tid == 0) acc_s += red[0] / g_poscnt[b];
        __syncthreads();
    }
    if (tid == 0) out[0] = acc_s / (float)B;
}

// ===========================================================================
extern "C" void kernel_launch(void* const* d_in, const int* in_sizes, int n_in,
                              void* d_out, int out_size) {
    const float* f  = (const float*)d_in[0];   // (B,C,D) fp32
    const float* p  = (const float*)d_in[1];   // (C,D)   fp32
    const int*   tg = (const int*)d_in[2];     // (B,C)   int32 (or int64; probed)
    const float* rs = (const float*)d_in[3];   // (B,C)   fp32
    float* out = (float*)d_out;

    k_setup<<<17, 1024>>>(tg);
    k_prep<<<1056, 1024>>>(p, tg, rs);
    k_gemm<<<GEMM_BLOCKS, 256>>>(f);
    k_select<<<SEL_BLOCKS, 1024>>>(tg);
    k_final<<<1, 256>>>(out);
}

// round 9
// speedup vs baseline: 2.1876x; 1.2386x over previous
#include <cuda_runtime.h>
#include <math.h>
#include <math_constants.h>

// Problem constants (shapes fixed by setup_inputs)
#define B 16
#define C 1024
#define D 768
#define KH 306          // int((C-1) * 0.3)
#define KR 717          // (C-1) - KH
#define TAUF 0.1f
#define GG 12           // anchors per GEMM group
#define KHALF 384       // k-split: each GEMM item does half the D dimension
#define GEMM_BLOCKS 148
#define SEL_BLOCKS 304

// ---- device scratch (module globals; no runtime allocation) ----
__device__ float          g_pT[D * C];              // protos transposed [k][c] (unnormalized)
__device__ float          g_pinv[C];                // 1/max(||p_c||,eps)
__device__ float          g_sims[B * C * 2 * C];    // partial sims: [listpos][half][C]
__device__ float          g_loss[B * C];
__device__ unsigned char  g_randmem[B * C];
__device__ float          g_poscnt[B];
__device__ int            g_list[B * C];
__device__ int            g_npos;
__device__ int            g_tstride;                // 1 = int32 targets, 2 = int64

// packed f32x2 FMA: d.lo = a.lo*b.lo + c.lo ; d.hi = a.hi*b.hi + c.hi
__device__ __forceinline__ unsigned long long ffma2(unsigned long long a,
                                                    unsigned long long b,
                                                    unsigned long long c) {
    unsigned long long d;
    asm("fma.rn.f32x2 %0, %1, %2, %3;" : "=l"(d) : "l"(a), "l"(b), "l"(c));
    return d;
}

// ===========================================================================
// setup: zero g_loss; one block probes targets dtype + zeroes g_npos.
__global__ void k_setup(const int* __restrict__ tgw) {
    int tid = threadIdx.x;
    int blk = blockIdx.x;
    if (blk < 16) {
        g_loss[blk * 1024 + tid] = 0.f;
    } else {
        __shared__ int flag;
        if (tid == 0) flag = 0;
        __syncthreads();
        bool nz = false;
#pragma unroll
        for (int k = 0; k < 8; k++) nz |= (tgw[2 * (tid + k * 1024) + 1] != 0);
        if (nz) flag = 1;
        __syncthreads();
        if (tid == 0) { g_tstride = flag ? 1 : 2; g_npos = 0; }
    }
}

// ===========================================================================
// Radix-select: Ksel-th largest among 1024 per-thread keys (key==0 excluded).
// Exit: *sh_prefix = threshold key T, *sh_rem = #elements equal to T in top-Ksel.
__device__ __forceinline__ void radix_select_desc(
    unsigned key, int Ksel,
    unsigned* hist, unsigned* S, unsigned* wtot,
    unsigned* sh_prefix, unsigned* sh_rem,
    int tid, int lane)
{
    if (tid == 0) { *sh_prefix = 0u; *sh_rem = (unsigned)Ksel; }
    __syncthreads();
#pragma unroll
    for (int byte = 3; byte >= 0; byte--) {
        int shift = byte * 8;
        if (tid < 256) hist[tid] = 0u;
        __syncthreads();
        unsigned pfx = *sh_prefix;
        bool match = (byte == 3) || ((key >> (shift + 8)) == (pfx >> (shift + 8)));
        if (match && key != 0u) atomicAdd(&hist[(key >> shift) & 255u], 1u);
        __syncthreads();
        if (tid < 256) {
            unsigned v = hist[tid];
#pragma unroll
            for (int d = 1; d < 32; d <<= 1) {          // warp suffix scan
                unsigned t2 = __shfl_down_sync(0xFFFFFFFFu, v, d);
                if (lane + d < 32) v += t2;
            }
            S[tid] = v;
            if (lane == 0) wtot[tid >> 5] = v;
        }
        __syncthreads();
        unsigned remloc = *sh_rem;
        if (tid < 256) {
            unsigned ws = 0;
            for (int w = (tid >> 5) + 1; w < 8; w++) ws += wtot[w];
            S[tid] += ws;
        }
        __syncthreads();
        if (tid < 256) {
            unsigned st = S[tid];
            unsigned snext = (tid == 255) ? 0u : S[tid + 1];
            if (st >= remloc && snext < remloc) {
                *sh_prefix = pfx | ((unsigned)tid << shift);
                *sh_rem = remloc - snext;
            }
        }
        __syncthreads();
    }
}

// ===========================================================================
// prep (1024 threads/block):
//   blocks [0,768)    : coalesced 32x33 tile transpose p -> g_pT (no norm)
//   blocks [768,800)  : row norms -> g_pinv (warp per proto row)
//   blocks [800,816)  : rand-negative membership per batch elem
//   blocks [816,832)  : compact positive anchors
__global__ void __launch_bounds__(1024) k_prep(const float* __restrict__ p,
                                               const int* __restrict__ tg,
                                               const float* __restrict__ rs) {
    __shared__ float tile[32][33];
    __shared__ unsigned hist[256];
    __shared__ unsigned S[256];
    __shared__ unsigned wtot[32];
    __shared__ unsigned sh_prefix, sh_rem;

    int tid = threadIdx.x;
    int lane = tid & 31, wid = tid >> 5;
    int blk = blockIdx.x;

    if (blk < 768) {
        // ---- transpose tile: j-tile = blk&31, k-tile = blk>>5 (24 of them) ----
        int tx = blk & 31;   // proto-row tile (C dim)
        int ty = blk >> 5;   // feature tile  (D dim)
        tile[wid][lane] = p[(tx * 32 + wid) * D + ty * 32 + lane];
        __syncthreads();
        g_pT[(ty * 32 + wid) * C + tx * 32 + lane] = tile[lane][wid];
    } else if (blk < 800) {
        // ---- row norms: warp per proto row ----
        int j = (blk - 768) * 32 + wid;
        const float* pr = p + (size_t)j * D;
        float ss = 0.f;
#pragma unroll
        for (int t = 0; t < 24; t++) {
            float v = pr[lane + 32 * t];
            ss += v * v;
        }
#pragma unroll
        for (int d = 16; d > 0; d >>= 1) ss += __shfl_xor_sync(0xFFFFFFFFu, ss, d);
        if (lane == 0) g_pinv[j] = 1.f / fmaxf(sqrtf(ss), 1e-12f);
    } else if (blk < 816) {
        // ---- rand-negative membership for batch b ----
        int b = blk - 800;
        int ts = g_tstride;
        bool posc = (tg[(b * C + tid) * ts] != 0);
        float r = rs[b * C + tid];
        unsigned key = posc ? 0u : (__float_as_uint(r) + 1u);  // monotone, >0

        unsigned bal = __ballot_sync(0xFFFFFFFFu, posc);
        if (lane == 0) wtot[wid] = (unsigned)__popc(bal);
        __syncthreads();
        if (tid == 0) {
            unsigned cnt = 0;
            for (int w = 0; w < 32; w++) cnt += wtot[w];
            g_poscnt[b] = (float)(cnt > 0 ? cnt : 1u);
        }
        __syncthreads();

        radix_select_desc(key, KR, hist, S, wtot, &sh_prefix, &sh_rem, tid, lane);
        unsigned T = sh_prefix;
        unsigned remf = sh_rem;

        // tie resolution by lowest index (matches jax.lax.top_k stability)
        bool eq = (key == T) && (key != 0u);
        unsigned eb = __ballot_sync(0xFFFFFFFFu, eq);
        if (lane == 0) wtot[wid] = (unsigned)__popc(eb);
        __syncthreads();
        unsigned off = 0;
        for (int w = 0; w < wid; w++) off += wtot[w];
        unsigned rank = off + (unsigned)__popc(eb & ((1u << lane) - 1u));
        bool in = (key != 0u) && ((key > T) || (eq && rank < remf));
        g_randmem[b * C + tid] = in ? (unsigned char)1 : (unsigned char)0;
    } else {
        // ---- compact positive anchors for batch b ----
        int b = blk - 816;
        int ts = g_tstride;
        int a = b * C + tid;
        if (tg[a * ts] != 0) {
            int pidx = atomicAdd(&g_npos, 1);
            g_list[pidx] = a;
        }
    }
}

// ===========================================================================
// GEMM: items = (anchor group of GG) x (k-half). 256 threads, 4 cols/thread,
// f rows pre-duplicated {v,v} in smem, inner loop = LDS.64-bcast + FFMA2.
__global__ void __launch_bounds__(256) k_gemm(const float* __restrict__ f) {
    __shared__ unsigned long long f2_s[GG][KHALF];   // 36,864 B
    __shared__ int s_anchor[GG];

    int tid = threadIdx.x;
    int wid = tid >> 5, lane = tid & 31;
    int npos = g_npos;
    int ng = (npos + GG - 1) / GG;
    int nitems = ng * 2;

    for (int item = blockIdx.x; item < nitems; item += GEMM_BLOCKS) {
        int grp = item >> 1;
        int half = item & 1;
        __syncthreads();   // previous iter's f2_s reads done
        if (tid < GG) {
            int idx = grp * GG + tid;
            s_anchor[tid] = (idx < npos) ? g_list[idx] : -1;
        }
        __syncthreads();

        // warps normalize anchors (full-row norm), write duplicated half rows
        for (int u = wid; u < GG; u += 8) {
            int a = s_anchor[u];
            float vs[24];
            float ss = 0.f;
            if (a >= 0) {
                const float* fr = f + (size_t)a * D;
#pragma unroll
                for (int t = 0; t < 24; t++) {
                    float v = fr[lane + 32 * t];
                    vs[t] = v; ss += v * v;
                }
            } else {
#pragma unroll
                for (int t = 0; t < 24; t++) vs[t] = 0.f;
            }
#pragma unroll
            for (int d = 16; d > 0; d >>= 1) ss += __shfl_xor_sync(0xFFFFFFFFu, ss, d);
            float inv = (1.f / fmaxf(sqrtf(ss), 1e-12f)) * (1.f / TAUF);
#pragma unroll
            for (int t = 0; t < 12; t++) {
                unsigned vb = __float_as_uint(vs[half * 12 + t] * inv);
                f2_s[u][lane + 32 * t] = ((unsigned long long)vb << 32) | vb;
            }
        }
        __syncthreads();

        int col = 4 * tid;
        const float* pc = g_pT + (size_t)half * KHALF * C + col;
        unsigned long long accA[GG], accB[GG];
#pragma unroll
        for (int u = 0; u < GG; u++) { accA[u] = 0ull; accB[u] = 0ull; }

#pragma unroll 2
        for (int k = 0; k < KHALF; k++) {
            union { float4 v; unsigned long long ll[2]; } pu;
            pu.v = *(const float4*)(pc + (size_t)k * C);
#pragma unroll
            for (int u = 0; u < GG; u++) {
                unsigned long long fv = f2_s[u][k];
                accA[u] = ffma2(fv, pu.ll[0], accA[u]);
                accB[u] = ffma2(fv, pu.ll[1], accB[u]);
            }
        }

        float4 pinv = *(const float4*)(g_pinv + col);
        int base = grp * GG;
#pragma unroll
        for (int u = 0; u < GG; u++) {
            if (base + u < npos) {
                float2 a2 = *(float2*)&accA[u];
                float2 b2 = *(float2*)&accB[u];
                float4 o;
                o.x = a2.x * pinv.x; o.y = a2.y * pinv.y;
                o.z = b2.x * pinv.z; o.w = b2.y * pinv.w;
                *(float4*)&g_sims[(size_t)(base + u) * 2048 + half * 1024 + col] = o;
            }
        }
    }
}

// ===========================================================================
// select+loss: one item per anchor, 1024 threads (one column each).
__global__ void __launch_bounds__(1024) k_select(const int* __restrict__ tg) {
    __shared__ unsigned hist[256];
    __shared__ unsigned S[256];
    __shared__ unsigned wtot[32];
    __shared__ unsigned sh_prefix, sh_rem;
    __shared__ unsigned u_red[32];
    __shared__ float f_red[32];
    __shared__ float s_vT, s_possim;

    int tid = threadIdx.x;
    int lane = tid & 31, wid = tid >> 5;
    int npos = g_npos;
    int ts = g_tstride;

    for (int i = blockIdx.x; i < npos; i += SEL_BLOCKS) {
        int a = g_list[i];
        int b = a >> 10;
        int c = a & (C - 1);

        float sim = g_sims[(size_t)i * 2048 + tid] +
                    g_sims[(size_t)i * 2048 + 1024 + tid];
        bool posc = (tg[(b * C + tid) * ts] != 0);
        unsigned bits = __float_as_uint(sim);
        unsigned key = posc ? 0u
                            : (bits ^ ((bits & 0x80000000u) ? 0xFFFFFFFFu : 0x80000000u));
        if (tid == c) s_possim = sim;

        // max negative sim
        unsigned mk = key;
#pragma unroll
        for (int d = 16; d > 0; d >>= 1) mk = max(mk, __shfl_xor_sync(0xFFFFFFFFu, mk, d));
        if (lane == 0) u_red[wid] = mk;
        __syncthreads();
        if (tid < 32) {
            unsigned t = u_red[tid];
#pragma unroll
            for (int d = 16; d > 0; d >>= 1) t = max(t, __shfl_xor_sync(0xFFFFFFFFu, t, d));
            if (tid == 0) u_red[0] = t;
        }
        __syncthreads();
        unsigned maxkey = u_red[0];
        unsigned mbits = (maxkey & 0x80000000u) ? (maxkey ^ 0x80000000u) : ~maxkey;
        float m = __uint_as_float(mbits);

        radix_select_desc(key, KH, hist, S, wtot, &sh_prefix, &sh_rem, tid, lane);
        unsigned T = sh_prefix;
        unsigned remf = sh_rem;

        float contrib = 0.f;
        if (key > T) contrib = expf(sim - m);
        if (key == T && key != 0u) s_vT = sim;     // benign: all writers equal
        if (g_randmem[b * C + tid]) contrib += expf(sim - m);
        __syncthreads();

#pragma unroll
        for (int d = 16; d > 0; d >>= 1) contrib += __shfl_xor_sync(0xFFFFFFFFu, contrib, d);
        if (lane == 0) f_red[wid] = contrib;
        __syncthreads();
        if (tid == 0) {
            float tot = 0.f;
            for (int w = 0; w < 32; w++) tot += f_red[w];
            tot += (float)remf * expf(s_vT - m);
            float lse = m + logf(tot);
            float x = lse - s_possim;
            g_loss[a] = fmaxf(x, 0.f) + log1pf(expf(-fabsf(x)));
        }
        __syncthreads();
    }
}

// ===========================================================================
// final: deterministic fixed-order reduction to the scalar loss.
__global__ void k_final(float* __restrict__ out) {
    __shared__ float red[256];
    __shared__ float acc_s;
    int tid = threadIdx.x;
    if (tid == 0) acc_s = 0.f;
    __syncthreads();
    for (int b = 0; b < B; b++) {
        float p = 0.f;
        for (int c = tid; c < C; c += 256) p += g_loss[b * C + c];
        red[tid] = p;
        __syncthreads();
        for (int s = 128; s > 0; s >>= 1) {
            if (tid < s) red[tid] += red[tid + s];
            __syncthreads();
        }
        if (tid == 0) acc_s += red[0] / g_poscnt[b];
        __syncthreads();
    }
    if (tid == 0) out[0] = acc_s / (float)B;
}

// ===========================================================================
extern "C" void kernel_launch(void* const* d_in, const int* in_sizes, int n_in,
                              void* d_out, int out_size) {
    const float* f  = (const float*)d_in[0];   // (B,C,D) fp32
    const float* p  = (const float*)d_in[1];   // (C,D)   fp32
    const int*   tg = (const int*)d_in[2];     // (B,C)   int32 (or int64; probed)
    const float* rs = (const float*)d_in[3];   // (B,C)   fp32
    float* out = (float*)d_out;

    k_setup<<<17, 1024>>>(tg);
    k_prep<<<832, 1024>>>(p, tg, rs);
    k_gemm<<<GEMM_BLOCKS, 256>>>(f);
    k_select<<<SEL_BLOCKS, 1024>>>(tg);
    k_final<<<1, 256>>>(out);
}

// round 11
// speedup vs baseline: 3.3024x; 1.5096x over previous
#include <cuda_runtime.h>
#include <math.h>
#include <math_constants.h>

// Problem constants (shapes fixed by setup_inputs)
#define B 16
#define C 1024
#define D 768
#define KH 306          // int((C-1) * 0.3)
#define KR 717          // (C-1) - KH
#define TAUF 0.1f
#define GG 12           // anchors per GEMM group
#define KSPLIT 4        // k-split factor
#define KQ 192          // D / KSPLIT
#define GEMM_BLOCKS 276
#define SEL_BLOCKS 304

// ---- device scratch (module globals; no runtime allocation) ----
__device__ float          g_pT[D * C];                   // protos transposed [k][c] (unnormalized)
__device__ float          g_pinv[C];                     // 1/max(||p_c||,eps)
__device__ float          g_sims[B * C * KSPLIT * C];    // partial sims: [listpos][q][C]
__device__ float          g_loss[B * C];
__device__ unsigned char  g_randmem[B * C];
__device__ float          g_poscnt[B];
__device__ int            g_list[B * C];
__device__ int            g_npos;
__device__ int            g_tstride;                     // 1 = int32 targets, 2 = int64

// packed f32x2 FMA: d.lo = a.lo*b.lo + c.lo ; d.hi = a.hi*b.hi + c.hi
__device__ __forceinline__ unsigned long long ffma2(unsigned long long a,
                                                    unsigned long long b,
                                                    unsigned long long c) {
    unsigned long long d;
    asm("fma.rn.f32x2 %0, %1, %2, %3;" : "=l"(d) : "l"(a), "l"(b), "l"(c));
    return d;
}

// ===========================================================================
// setup: zero g_loss; one block probes targets dtype + zeroes g_npos.
__global__ void k_setup(const int* __restrict__ tgw) {
    int tid = threadIdx.x;
    int blk = blockIdx.x;
    if (blk < 16) {
        g_loss[blk * 1024 + tid] = 0.f;
    } else {
        __shared__ int flag;
        if (tid == 0) flag = 0;
        __syncthreads();
        bool nz = false;
#pragma unroll
        for (int k = 0; k < 8; k++) nz |= (tgw[2 * (tid + k * 1024) + 1] != 0);
        if (nz) flag = 1;
        __syncthreads();
        if (tid == 0) { g_tstride = flag ? 1 : 2; g_npos = 0; }
    }
}

// ===========================================================================
// Radix-select: Ksel-th largest among 1024 per-thread keys (key==0 excluded).
// Exit: *sh_prefix = threshold key T, *sh_rem = #elements equal to T in top-Ksel.
__device__ __forceinline__ void radix_select_desc(
    unsigned key, int Ksel,
    unsigned* hist, unsigned* S, unsigned* wtot,
    unsigned* sh_prefix, unsigned* sh_rem,
    int tid, int lane)
{
    if (tid == 0) { *sh_prefix = 0u; *sh_rem = (unsigned)Ksel; }
    __syncthreads();
#pragma unroll
    for (int byte = 3; byte >= 0; byte--) {
        int shift = byte * 8;
        if (tid < 256) hist[tid] = 0u;
        __syncthreads();
        unsigned pfx = *sh_prefix;
        bool match = (byte == 3) || ((key >> (shift + 8)) == (pfx >> (shift + 8)));
        if (match && key != 0u) atomicAdd(&hist[(key >> shift) & 255u], 1u);
        __syncthreads();
        if (tid < 256) {
            unsigned v = hist[tid];
#pragma unroll
            for (int d = 1; d < 32; d <<= 1) {          // warp suffix scan
                unsigned t2 = __shfl_down_sync(0xFFFFFFFFu, v, d);
                if (lane + d < 32) v += t2;
            }
            S[tid] = v;
            if (lane == 0) wtot[tid >> 5] = v;
        }
        __syncthreads();
        unsigned remloc = *sh_rem;
        if (tid < 256) {
            unsigned ws = 0;
            for (int w = (tid >> 5) + 1; w < 8; w++) ws += wtot[w];
            S[tid] += ws;
        }
        __syncthreads();
        if (tid < 256) {
            unsigned st = S[tid];
            unsigned snext = (tid == 255) ? 0u : S[tid + 1];
            if (st >= remloc && snext < remloc) {
                *sh_prefix = pfx | ((unsigned)tid << shift);
                *sh_rem = remloc - snext;
            }
        }
        __syncthreads();
    }
}

// ===========================================================================
// prep (1024 threads/block):
//   blocks [0,768)    : coalesced 32x33 tile transpose p -> g_pT (no norm)
//   blocks [768,800)  : row norms -> g_pinv (warp per proto row)
//   blocks [800,816)  : rand-negative membership per batch elem
//   blocks [816,832)  : compact positive anchors
__global__ void __launch_bounds__(1024) k_prep(const float* __restrict__ p,
                                               const int* __restrict__ tg,
                                               const float* __restrict__ rs) {
    __shared__ float tile[32][33];
    __shared__ unsigned hist[256];
    __shared__ unsigned S[256];
    __shared__ unsigned wtot[32];
    __shared__ unsigned sh_prefix, sh_rem;

    int tid = threadIdx.x;
    int lane = tid & 31, wid = tid >> 5;
    int blk = blockIdx.x;

    if (blk < 768) {
        int tx = blk & 31;   // proto-row tile (C dim)
        int ty = blk >> 5;   // feature tile  (D dim)
        tile[wid][lane] = p[(tx * 32 + wid) * D + ty * 32 + lane];
        __syncthreads();
        g_pT[(ty * 32 + wid) * C + tx * 32 + lane] = tile[lane][wid];
    } else if (blk < 800) {
        int j = (blk - 768) * 32 + wid;
        const float* pr = p + (size_t)j * D;
        float ss = 0.f;
#pragma unroll
        for (int t = 0; t < 24; t++) {
            float v = pr[lane + 32 * t];
            ss += v * v;
        }
#pragma unroll
        for (int d = 16; d > 0; d >>= 1) ss += __shfl_xor_sync(0xFFFFFFFFu, ss, d);
        if (lane == 0) g_pinv[j] = 1.f / fmaxf(sqrtf(ss), 1e-12f);
    } else if (blk < 816) {
        int b = blk - 800;
        int ts = g_tstride;
        bool posc = (tg[(b * C + tid) * ts] != 0);
        float r = rs[b * C + tid];
        unsigned key = posc ? 0u : (__float_as_uint(r) + 1u);  // monotone, >0

        unsigned bal = __ballot_sync(0xFFFFFFFFu, posc);
        if (lane == 0) wtot[wid] = (unsigned)__popc(bal);
        __syncthreads();
        if (tid == 0) {
            unsigned cnt = 0;
            for (int w = 0; w < 32; w++) cnt += wtot[w];
            g_poscnt[b] = (float)(cnt > 0 ? cnt : 1u);
        }
        __syncthreads();

        radix_select_desc(key, KR, hist, S, wtot, &sh_prefix, &sh_rem, tid, lane);
        unsigned T = sh_prefix;
        unsigned remf = sh_rem;

        bool eq = (key == T) && (key != 0u);
        unsigned eb = __ballot_sync(0xFFFFFFFFu, eq);
        if (lane == 0) wtot[wid] = (unsigned)__popc(eb);
        __syncthreads();
        unsigned off = 0;
        for (int w = 0; w < wid; w++) off += wtot[w];
        unsigned rank = off + (unsigned)__popc(eb & ((1u << lane) - 1u));
        bool in = (key != 0u) && ((key > T) || (eq && rank < remf));
        g_randmem[b * C + tid] = in ? (unsigned char)1 : (unsigned char)0;
    } else {
        int b = blk - 816;
        int ts = g_tstride;
        int a = b * C + tid;
        if (tg[a * ts] != 0) {
            int pidx = atomicAdd(&g_npos, 1);
            g_list[pidx] = a;
        }
    }
}

// ===========================================================================
// GEMM: items = (anchor group of GG) x (k-quarter). 256 threads, 4 cols/thread,
// f rows pre-duplicated {v,v} in smem, inner loop = LDS.64-bcast + FFMA2.
// 18.4 KB smem -> 2 co-resident blocks/SM (4 warps/SMSP) for latency hiding.
__global__ void __launch_bounds__(256) k_gemm(const float* __restrict__ f) {
    __shared__ unsigned long long f2_s[GG][KQ];   // 18,432 B
    __shared__ int s_anchor[GG];

    int tid = threadIdx.x;
    int wid = tid >> 5, lane = tid & 31;
    int npos = g_npos;
    int ng = (npos + GG - 1) / GG;
    int nitems = ng * KSPLIT;

    for (int item = blockIdx.x; item < nitems; item += GEMM_BLOCKS) {
        int grp = item >> 2;
        int quarter = item & 3;
        __syncthreads();   // previous iter's f2_s reads done
        if (tid < GG) {
            int idx = grp * GG + tid;
            s_anchor[tid] = (idx < npos) ? g_list[idx] : -1;
        }
        __syncthreads();

        // warps normalize anchors (full-row norm), write duplicated quarter rows
        for (int u = wid; u < GG; u += 8) {
            int a = s_anchor[u];
            float vs[24];
            float ss = 0.f;
            if (a >= 0) {
                const float* fr = f + (size_t)a * D;
#pragma unroll
                for (int t = 0; t < 24; t++) {
                    float v = fr[lane + 32 * t];
                    vs[t] = v; ss += v * v;
                }
            } else {
#pragma unroll
                for (int t = 0; t < 24; t++) vs[t] = 0.f;
            }
#pragma unroll
            for (int d = 16; d > 0; d >>= 1) ss += __shfl_xor_sync(0xFFFFFFFFu, ss, d);
            float inv = (1.f / fmaxf(sqrtf(ss), 1e-12f)) * (1.f / TAUF);
#pragma unroll
            for (int t = 0; t < 6; t++) {
                unsigned vb = __float_as_uint(vs[quarter * 6 + t] * inv);
                f2_s[u][lane + 32 * t] = ((unsigned long long)vb << 32) | vb;
            }
        }
        __syncthreads();

        int col = 4 * tid;
        const float* pc = g_pT + (size_t)quarter * KQ * C + col;
        unsigned long long accA[GG], accB[GG];
#pragma unroll
        for (int u = 0; u < GG; u++) { accA[u] = 0ull; accB[u] = 0ull; }

#pragma unroll 4
        for (int k = 0; k < KQ; k++) {
            union { float4 v; unsigned long long ll[2]; } pu;
            pu.v = *(const float4*)(pc + (size_t)k * C);
#pragma unroll
            for (int u = 0; u < GG; u++) {
                unsigned long long fv = f2_s[u][k];
                accA[u] = ffma2(fv, pu.ll[0], accA[u]);
                accB[u] = ffma2(fv, pu.ll[1], accB[u]);
            }
        }

        float4 pinv = *(const float4*)(g_pinv + col);
        int base = grp * GG;
#pragma unroll
        for (int u = 0; u < GG; u++) {
            if (base + u < npos) {
                float2 a2 = *(float2*)&accA[u];
                float2 b2 = *(float2*)&accB[u];
                float4 o;
                o.x = a2.x * pinv.x; o.y = a2.y * pinv.y;
                o.z = b2.x * pinv.z; o.w = b2.y * pinv.w;
                *(float4*)&g_sims[(size_t)(base + u) * (KSPLIT * 1024) +
                                  quarter * 1024 + col] = o;
            }
        }
    }
}

// ===========================================================================
// select+loss: one item per anchor, 1024 threads (one column each).
__global__ void __launch_bounds__(1024) k_select(const int* __restrict__ tg) {
    __shared__ unsigned hist[256];
    __shared__ unsigned S[256];
    __shared__ unsigned wtot[32];
    __shared__ unsigned sh_prefix, sh_rem;
    __shared__ unsigned u_red[32];
    __shared__ float f_red[32];
    __shared__ float s_vT, s_possim;

    int tid = threadIdx.x;
    int lane = tid & 31, wid = tid >> 5;
    int npos = g_npos;
    int ts = g_tstride;

    for (int i = blockIdx.x; i < npos; i += SEL_BLOCKS) {
        int a = g_list[i];
        int b = a >> 10;
        int c = a & (C - 1);

        const float* sp = g_sims + (size_t)i * (KSPLIT * 1024) + tid;
        float sim = ((sp[0] + sp[1024]) + (sp[2048] + sp[3072]));
        bool posc = (tg[(b * C + tid) * ts] != 0);
        unsigned bits = __float_as_uint(sim);
        unsigned key = posc ? 0u
                            : (bits ^ ((bits & 0x80000000u) ? 0xFFFFFFFFu : 0x80000000u));
        if (tid == c) s_possim = sim;

        // max negative sim
        unsigned mk = key;
#pragma unroll
        for (int d = 16; d > 0; d >>= 1) mk = max(mk, __shfl_xor_sync(0xFFFFFFFFu, mk, d));
        if (lane == 0) u_red[wid] = mk;
        __syncthreads();
        if (tid < 32) {
            unsigned t = u_red[tid];
#pragma unroll
            for (int d = 16; d > 0; d >>= 1) t = max(t, __shfl_xor_sync(0xFFFFFFFFu, t, d));
            if (tid == 0) u_red[0] = t;
        }
        __syncthreads();
        unsigned maxkey = u_red[0];
        unsigned mbits = (maxkey & 0x80000000u) ? (maxkey ^ 0x80000000u) : ~maxkey;
        float m = __uint_as_float(mbits);

        radix_select_desc(key, KH, hist, S, wtot, &sh_prefix, &sh_rem, tid, lane);
        unsigned T = sh_prefix;
        unsigned remf = sh_rem;

        float contrib = 0.f;
        if (key > T) contrib = expf(sim - m);
        if (key == T && key != 0u) s_vT = sim;     // benign: all writers equal
        if (g_randmem[b * C + tid]) contrib += expf(sim - m);
        __syncthreads();

#pragma unroll
        for (int d = 16; d > 0; d >>= 1) contrib += __shfl_xor_sync(0xFFFFFFFFu, contrib, d);
        if (lane == 0) f_red[wid] = contrib;
        __syncthreads();
        if (tid == 0) {
            float tot = 0.f;
            for (int w = 0; w < 32; w++) tot += f_red[w];
            tot += (float)remf * expf(s_vT - m);
            float lse = m + logf(tot);
            float x = lse - s_possim;
            g_loss[a] = fmaxf(x, 0.f) + log1pf(expf(-fabsf(x)));
        }
        __syncthreads();
    }
}

// ===========================================================================
// final: deterministic fixed-order reduction to the scalar loss.
__global__ void k_final(float* __restrict__ out) {
    __shared__ float red[256];
    __shared__ float acc_s;
    int tid = threadIdx.x;
    if (tid == 0) acc_s = 0.f;
    __syncthreads();
    for (int b = 0; b < B; b++) {
        float p = 0.f;
        for (int c = tid; c < C; c += 256) p += g_loss[b * C + c];
        red[tid] = p;
        __syncthreads();
        for (int s = 128; s > 0; s >>= 1) {
            if (tid < s) red[tid] += red[tid + s];
            __syncthreads();
        }
        if (tid == 0) acc_s += red[0] / g_poscnt[b];
        __syncthreads();
    }
    if (tid == 0) out[0] = acc_s / (float)B;
}

// ===========================================================================
extern "C" void kernel_launch(void* const* d_in, const int* in_sizes, int n_in,
                              void* d_out, int out_size) {
    const float* f  = (const float*)d_in[0];   // (B,C,D) fp32
    const float* p  = (const float*)d_in[1];   // (C,D)   fp32
    const int*   tg = (const int*)d_in[2];     // (B,C)   int32 (or int64; probed)
    const float* rs = (const float*)d_in[3];   // (B,C)   fp32
    float* out = (float*)d_out;

    k_setup<<<17, 1024>>>(tg);
    k_prep<<<832, 1024>>>(p, tg, rs);
    k_gemm<<<GEMM_BLOCKS, 256>>>(f);
    k_select<<<SEL_BLOCKS, 1024>>>(tg);
    k_final<<<1, 256>>>(out);
}

// round 12
// speedup vs baseline: 3.6795x; 1.1142x over previous
#include <cuda_runtime.h>
#include <math.h>
#include <math_constants.h>

// Problem constants (shapes fixed by setup_inputs)
#define B 16
#define C 1024
#define D 768
#define KH 306          // int((C-1) * 0.3)
#define KR 717          // (C-1) - KH
#define TAUF 0.1f
#define GG 12           // anchors per GEMM group
#define KSPLIT 4        // k-split factor
#define KQ 192          // D / KSPLIT
#define GEMM_BLOCKS 276
#define SEL_BLOCKS 256

// ---- device scratch (module globals; no runtime allocation) ----
__device__ float          g_pT[D * C];                   // protos transposed [k][c] (unnormalized)
__device__ float          g_pinv[C];                     // 1/max(||p_c||,eps)
__device__ float          g_sims[B * C * KSPLIT * C];    // partial sims: [listpos][q][C]
__device__ float          g_lossd[B * C];                // per-positive loss, dense by list pos
__device__ unsigned char  g_mask[B * C];                 // bit0 = rand-negative, bit1 = positive
__device__ float          g_poscnt[B];                   // clip(count,1)
__device__ int            g_cnt[B];                      // positives per batch (overwritten每launch)
__device__ int            g_list[B * 1024];              // column index of each positive, per batch

// packed f32x2 FMA
__device__ __forceinline__ unsigned long long ffma2(unsigned long long a,
                                                    unsigned long long b,
                                                    unsigned long long c) {
    unsigned long long d;
    asm("fma.rn.f32x2 %0, %1, %2, %3;" : "=l"(d) : "l"(a), "l"(b), "l"(c));
    return d;
}

// named barrier for a 256-thread group
__device__ __forceinline__ void gbar(int id) {
    asm volatile("bar.sync %0, 256;" :: "r"(id) : "memory");
}

// ===========================================================================
// Block-wide (1024-thread) radix select: Ksel-th largest among keys (0=excl).
__device__ __forceinline__ void radix_select_desc(
    unsigned key, int Ksel,
    unsigned* hist, unsigned* S, unsigned* wtot,
    unsigned* sh_prefix, unsigned* sh_rem,
    int tid, int lane)
{
    if (tid == 0) { *sh_prefix = 0u; *sh_rem = (unsigned)Ksel; }
    __syncthreads();
#pragma unroll
    for (int byte = 3; byte >= 0; byte--) {
        int shift = byte * 8;
        if (tid < 256) hist[tid] = 0u;
        __syncthreads();
        unsigned pfx = *sh_prefix;
        bool match = (byte == 3) || ((key >> (shift + 8)) == (pfx >> (shift + 8)));
        if (match && key != 0u) atomicAdd(&hist[(key >> shift) & 255u], 1u);
        __syncthreads();
        if (tid < 256) {
            unsigned v = hist[tid];
#pragma unroll
            for (int d = 1; d < 32; d <<= 1) {
                unsigned t2 = __shfl_down_sync(0xFFFFFFFFu, v, d);
                if (lane + d < 32) v += t2;
            }
            S[tid] = v;
            if (lane == 0) wtot[tid >> 5] = v;
        }
        __syncthreads();
        unsigned remloc = *sh_rem;
        if (tid < 256) {
            unsigned ws = 0;
            for (int w = (tid >> 5) + 1; w < 8; w++) ws += wtot[w];
            S[tid] += ws;
        }
        __syncthreads();
        if (tid < 256) {
            unsigned st = S[tid];
            unsigned snext = (tid == 255) ? 0u : S[tid + 1];
            if (st >= remloc && snext < remloc) {
                *sh_prefix = pfx | ((unsigned)tid << shift);
                *sh_rem = remloc - snext;
            }
        }
        __syncthreads();
    }
}

// ===========================================================================
// Group (256-thread, 4 keys/thread) radix select with named barrier `barid`.
__device__ __forceinline__ void radix4(
    const unsigned key[4], int Ksel,
    unsigned* hist, unsigned* S, unsigned* wtot,
    volatile unsigned* sh_prefix, volatile unsigned* sh_rem,
    int gtid, int lane, int wg, int barid)
{
    if (gtid == 0) { *sh_prefix = 0u; *sh_rem = (unsigned)Ksel; }
    gbar(barid);
#pragma unroll
    for (int byte = 3; byte >= 0; byte--) {
        int shift = byte * 8;
        hist[gtid] = 0u;
        gbar(barid);
        unsigned pfx = *sh_prefix;
#pragma unroll
        for (int x = 0; x < 4; x++) {
            bool match = (byte == 3) || ((key[x] >> (shift + 8)) == (pfx >> (shift + 8)));
            if (match && key[x] != 0u) atomicAdd(&hist[(key[x] >> shift) & 255u], 1u);
        }
        gbar(barid);
        unsigned v = hist[gtid];
#pragma unroll
        for (int d = 1; d < 32; d <<= 1) {
            unsigned t2 = __shfl_down_sync(0xFFFFFFFFu, v, d);
            if (lane + d < 32) v += t2;
        }
        if (lane == 0) wtot[wg] = v;
        gbar(barid);
        unsigned remloc = *sh_rem;
        unsigned ws = 0;
        for (int w = wg + 1; w < 8; w++) ws += wtot[w];
        unsigned st = v + ws;            // suffix sum from this bin
        S[gtid] = st;
        gbar(barid);
        unsigned snext = (gtid == 255) ? 0u : S[gtid + 1];
        if (st >= remloc && snext < remloc) {
            *sh_prefix = pfx | ((unsigned)gtid << shift);
            *sh_rem = remloc - snext;
        }
        gbar(barid);
    }
}

// ===========================================================================
// prep (1024 threads/block):
//   [0,768)   : coalesced 32x33 tile transpose p -> g_pT
//   [768,800) : proto row norms -> g_pinv (warp per row)
//   [800,816) : rand-negative + positive mask byte per batch elem
//   [816,832) : rank-based positive compaction (no atomics, no reset needed)
// Each data-dependent block self-probes the targets dtype on its own row window.
__global__ void __launch_bounds__(1024) k_prep(const float* __restrict__ p,
                                               const int* __restrict__ tg,
                                               const float* __restrict__ rs) {
    __shared__ float tile[32][33];
    __shared__ unsigned hist[256];
    __shared__ unsigned S[256];
    __shared__ unsigned wtot[32];
    __shared__ unsigned sh_prefix, sh_rem;
    __shared__ int s_ts;

    int tid = threadIdx.x;
    int lane = tid & 31, wid = tid >> 5;
    int blk = blockIdx.x;

    if (blk < 768) {
        int tx = blk & 31;   // proto-row tile (C dim)
        int ty = blk >> 5;   // feature tile  (D dim)
        tile[wid][lane] = p[(tx * 32 + wid) * D + ty * 32 + lane];
        __syncthreads();
        g_pT[(ty * 32 + wid) * C + tx * 32 + lane] = tile[lane][wid];
        return;
    }
    if (blk < 800) {
        int j = (blk - 768) * 32 + wid;
        const float* pr = p + (size_t)j * D;
        float ss = 0.f;
#pragma unroll
        for (int t = 0; t < 24; t++) { float v = pr[lane + 32 * t]; ss += v * v; }
#pragma unroll
        for (int d = 16; d > 0; d >>= 1) ss += __shfl_xor_sync(0xFFFFFFFFu, ss, d);
        if (lane == 0) g_pinv[j] = 1.f / fmaxf(sqrtf(ss), 1e-12f);
        return;
    }

    // ---- dtype probe on this batch's word window [b*1024, b*1024+1024) ----
    int b = (blk < 816) ? (blk - 800) : (blk - 816);
    int w0 = tg[b * 1024 + tid];                       // word view; in-bounds either dtype
    bool oddnz = ((tid & 1) != 0) && (w0 != 0);
    unsigned ob = __ballot_sync(0xFFFFFFFFu, oddnz);
    if (lane == 0) wtot[wid] = ob ? 1u : 0u;
    __syncthreads();
    if (tid == 0) {
        unsigned fl = 0;
        for (int w = 0; w < 32; w++) fl |= wtot[w];
        s_ts = fl ? 1 : 2;                             // 1=int32, 2=int64
    }
    __syncthreads();
    int ts = s_ts;
    bool posc = (ts == 1) ? (w0 != 0) : (tg[(b * C + tid) * 2] != 0);
    __syncthreads();

    if (blk < 816) {
        // ---- rand-negative membership + mask byte ----
        float r = rs[b * C + tid];
        unsigned key = posc ? 0u : (__float_as_uint(r) + 1u);   // monotone, >0

        radix_select_desc(key, KR, hist, S, wtot, &sh_prefix, &sh_rem, tid, lane);
        unsigned T = sh_prefix;
        unsigned remf = sh_rem;

        // tie resolution by lowest index (matches jax.lax.top_k stability)
        bool eq = (key == T) && (key != 0u);
        unsigned eb = __ballot_sync(0xFFFFFFFFu, eq);
        if (lane == 0) wtot[wid] = (unsigned)__popc(eb);
        __syncthreads();
        unsigned off = 0;
        for (int w = 0; w < wid; w++) off += wtot[w];
        unsigned rank = off + (unsigned)__popc(eb & ((1u << lane) - 1u));
        bool in = (key != 0u) && ((key > T) || (eq && rank < remf));
        g_mask[b * C + tid] = (unsigned char)((posc ? 2 : 0) | (in ? 1 : 0));
    } else {
        // ---- rank-based compaction ----
        unsigned bal = __ballot_sync(0xFFFFFFFFu, posc);
        if (lane == 0) wtot[wid] = (unsigned)__popc(bal);
        __syncthreads();
        unsigned off = 0;
        for (int w = 0; w < wid; w++) off += wtot[w];
        unsigned rank = off + (unsigned)__popc(bal & ((1u << lane) - 1u));
        if (posc) g_list[b * 1024 + rank] = tid;
        if (tid == 0) {
            unsigned cnt = 0;
            for (int w = 0; w < 32; w++) cnt += wtot[w];
            g_cnt[b] = (int)cnt;
            g_poscnt[b] = (float)(cnt > 0 ? cnt : 1u);
        }
    }
}

// ===========================================================================
// GEMM: items = (anchor group of GG) x (k-quarter). 256 threads, 4 cols/thread,
// f rows pre-duplicated {v,v} in smem, inner loop = LDS.64-bcast + FFMA2.
__global__ void __launch_bounds__(256) k_gemm(const float* __restrict__ f) {
    __shared__ unsigned long long f2_s[GG][KQ];   // 18,432 B
    __shared__ int s_anchor[GG];
    __shared__ int s_pfx[17];

    int tid = threadIdx.x;
    int wid = tid >> 5, lane = tid & 31;

    if (tid == 0) {
        int acc = 0;
        for (int b = 0; b < B; b++) { s_pfx[b] = acc; acc += g_cnt[b]; }
        s_pfx[16] = acc;
    }
    __syncthreads();
    int npos = s_pfx[16];
    int ng = (npos + GG - 1) / GG;
    int nitems = ng * KSPLIT;

    for (int item = blockIdx.x; item < nitems; item += GEMM_BLOCKS) {
        int grp = item >> 2;
        int quarter = item & 3;
        __syncthreads();   // previous iter's f2_s reads done
        if (tid < GG) {
            int idx = grp * GG + tid;
            int aa = -1;
            if (idx < npos) {
                int bb = 0;
                while (bb < 15 && idx >= s_pfx[bb + 1]) bb++;
                aa = bb * C + g_list[bb * 1024 + (idx - s_pfx[bb])];
            }
            s_anchor[tid] = aa;
        }
        __syncthreads();

        for (int u = wid; u < GG; u += 8) {
            int a = s_anchor[u];
            float vs[24];
            float ss = 0.f;
            if (a >= 0) {
                const float* fr = f + (size_t)a * D;
#pragma unroll
                for (int t = 0; t < 24; t++) {
                    float v = fr[lane + 32 * t];
                    vs[t] = v; ss += v * v;
                }
            } else {
#pragma unroll
                for (int t = 0; t < 24; t++) vs[t] = 0.f;
            }
#pragma unroll
            for (int d = 16; d > 0; d >>= 1) ss += __shfl_xor_sync(0xFFFFFFFFu, ss, d);
            float inv = (1.f / fmaxf(sqrtf(ss), 1e-12f)) * (1.f / TAUF);
#pragma unroll
            for (int t = 0; t < 6; t++) {
                unsigned vb = __float_as_uint(vs[quarter * 6 + t] * inv);
                f2_s[u][lane + 32 * t] = ((unsigned long long)vb << 32) | vb;
            }
        }
        __syncthreads();

        int col = 4 * tid;
        const float* pc = g_pT + (size_t)quarter * KQ * C + col;
        unsigned long long accA[GG], accB[GG];
#pragma unroll
        for (int u = 0; u < GG; u++) { accA[u] = 0ull; accB[u] = 0ull; }

#pragma unroll 4
        for (int k = 0; k < KQ; k++) {
            union { float4 v; unsigned long long ll[2]; } pu;
            pu.v = *(const float4*)(pc + (size_t)k * C);
#pragma unroll
            for (int u = 0; u < GG; u++) {
                unsigned long long fv = f2_s[u][k];
                accA[u] = ffma2(fv, pu.ll[0], accA[u]);
                accB[u] = ffma2(fv, pu.ll[1], accB[u]);
            }
        }

        float4 pinv = *(const float4*)(g_pinv + col);
        int base = grp * GG;
#pragma unroll
        for (int u = 0; u < GG; u++) {
            if (base + u < npos) {
                float2 a2 = *(float2*)&accA[u];
                float2 b2 = *(float2*)&accB[u];
                float4 o;
                o.x = a2.x * pinv.x; o.y = a2.y * pinv.y;
                o.z = b2.x * pinv.z; o.w = b2.y * pinv.w;
                *(float4*)&g_sims[(size_t)(base + u) * (KSPLIT * 1024) +
                                  quarter * 1024 + col] = o;
            }
        }
    }
}

// ===========================================================================
// select+loss: 4 independent 256-thread groups per block (named barriers),
// 4 columns/thread, one radix-select per positive anchor.
__global__ void __launch_bounds__(1024) k_select() {
    __shared__ unsigned hist[4][256];
    __shared__ unsigned S[4][256];
    __shared__ unsigned wtot[4][8];
    __shared__ unsigned sh_prefix[4], sh_rem[4];
    __shared__ unsigned u_red[4][8];
    __shared__ float    f_red[4][8];
    __shared__ float    s_vT[4], s_possim[4];
    __shared__ int      s_pfx[17];

    int tid = threadIdx.x;
    int lane = tid & 31;
    int g = tid >> 8;            // group 0..3
    int gtid = tid & 255;
    int wg = (tid >> 5) & 7;     // warp within group
    int barid = g + 1;

    if (tid == 0) {
        int acc = 0;
        for (int b = 0; b < B; b++) { s_pfx[b] = acc; acc += g_cnt[b]; }
        s_pfx[16] = acc;
    }
    __syncthreads();
    int npos = s_pfx[16];

    for (int i = blockIdx.x * 4 + g; i < npos; i += SEL_BLOCKS * 4) {
        // anchor decode (redundant per thread; no sync needed)
        int bb = 0;
        while (bb < 15 && i >= s_pfx[bb + 1]) bb++;
        int c = g_list[bb * 1024 + (i - s_pfx[bb])];

        // load 4 columns of summed sims (fixed summation order)
        const float* sp = g_sims + (size_t)i * (KSPLIT * 1024) + 4 * gtid;
        float4 q0 = *(const float4*)(sp);
        float4 q1 = *(const float4*)(sp + 1024);
        float4 q2 = *(const float4*)(sp + 2048);
        float4 q3 = *(const float4*)(sp + 3072);
        float sim[4];
        sim[0] = (q0.x + q1.x) + (q2.x + q3.x);
        sim[1] = (q0.y + q1.y) + (q2.y + q3.y);
        sim[2] = (q0.z + q1.z) + (q2.z + q3.z);
        sim[3] = (q0.w + q1.w) + (q2.w + q3.w);

        uchar4 mk4 = *(const uchar4*)(g_mask + bb * C + 4 * gtid);
        unsigned char mk[4] = {mk4.x, mk4.y, mk4.z, mk4.w};

        unsigned key[4];
#pragma unroll
        for (int x = 0; x < 4; x++) {
            unsigned bits = __float_as_uint(sim[x]);
            unsigned flip = bits ^ ((bits & 0x80000000u) ? 0xFFFFFFFFu : 0x80000000u);
            key[x] = (mk[x] & 2) ? 0u : flip;
        }
        if ((c >> 2) == gtid) s_possim[g] = sim[c & 3];

        // max negative key -> m
        unsigned mx = max(max(key[0], key[1]), max(key[2], key[3]));
#pragma unroll
        for (int d = 16; d > 0; d >>= 1) mx = max(mx, __shfl_xor_sync(0xFFFFFFFFu, mx, d));
        if (lane == 0) u_red[g][wg] = mx;
        gbar(barid);
        unsigned maxkey = u_red[g][0];
#pragma unroll
        for (int w = 1; w < 8; w++) maxkey = max(maxkey, u_red[g][w]);
        unsigned mbits = (maxkey & 0x80000000u) ? (maxkey ^ 0x80000000u) : ~maxkey;
        float m = __uint_as_float(mbits);

        radix4(key, KH, hist[g], S[g], wtot[g], &sh_prefix[g], &sh_rem[g],
               gtid, lane, wg, barid);
        unsigned T = sh_prefix[g];
        unsigned remf = sh_rem[g];

        float contrib = 0.f;
#pragma unroll
        for (int x = 0; x < 4; x++) {
            float e = expf(sim[x] - m);
            if (key[x] > T) contrib += e;
            if (key[x] == T && key[x] != 0u) s_vT[g] = sim[x];  // equal keys = equal values
            if (mk[x] & 1) contrib += e;
        }
#pragma unroll
        for (int d = 16; d > 0; d >>= 1) contrib += __shfl_xor_sync(0xFFFFFFFFu, contrib, d);
        if (lane == 0) f_red[g][wg] = contrib;
        gbar(barid);
        if (gtid == 0) {
            float tot = 0.f;
            for (int w = 0; w < 8; w++) tot += f_red[g][w];
            tot += (float)remf * expf(s_vT[g] - m);
            float lse = m + logf(tot);
            float x = lse - s_possim[g];
            g_lossd[i] = fmaxf(x, 0.f) + log1pf(expf(-fabsf(x)));
        }
        gbar(barid);   // close iteration: protect s_possim / s_vT / smem reuse
    }
}

// ===========================================================================
// final: deterministic fixed-order reduction over dense per-positive losses.
__global__ void k_final(float* __restrict__ out) {
    __shared__ float red[256];
    __shared__ int s_pfx[17];
    __shared__ float acc_s;
    int tid = threadIdx.x;
    if (tid == 0) {
        int acc = 0;
        for (int b = 0; b < B; b++) { s_pfx[b] = acc; acc += g_cnt[b]; }
        s_pfx[16] = acc;
        acc_s = 0.f;
    }
    __syncthreads();
    for (int b = 0; b < B; b++) {
        float p = 0.f;
        for (int j = s_pfx[b] + tid; j < s_pfx[b + 1]; j += 256) p += g_lossd[j];
        red[tid] = p;
        __syncthreads();
        for (int s = 128; s > 0; s >>= 1) {
            if (tid < s) red[tid] += red[tid + s];
            __syncthreads();
        }
        if (tid == 0) acc_s += red[0] / g_poscnt[b];
        __syncthreads();
    }
    if (tid == 0) out[0] = acc_s / (float)B;
}

// ===========================================================================
extern "C" void kernel_launch(void* const* d_in, const int* in_sizes, int n_in,
                              void* d_out, int out_size) {
    const float* f  = (const float*)d_in[0];   // (B,C,D) fp32
    const float* p  = (const float*)d_in[1];   // (C,D)   fp32
    const int*   tg = (const int*)d_in[2];     // (B,C)   int32 (or int64; self-probed)
    const float* rs = (const float*)d_in[3];   // (B,C)   fp32
    float* out = (float*)d_out;

    k_prep<<<832, 1024>>>(p, tg, rs);
    k_gemm<<<GEMM_BLOCKS, 256>>>(f);
    k_select<<<SEL_BLOCKS, 1024>>>();
    k_final<<<1, 256>>>(out);
}

// round 13
// speedup vs baseline: 4.2106x; 1.1443x over previous
#include <cuda_runtime.h>
#include <math.h>
#include <math_constants.h>

// Problem constants (shapes fixed by setup_inputs)
#define B 16
#define C 1024
#define D 768
#define KH 306          // int((C-1) * 0.3)
#define KR 717          // (C-1) - KH
#define TAUF 0.1f
#define GG 12           // anchors per GEMM group
#define KSPLIT 4        // k-split factor
#define KQ 192          // D / KSPLIT
#define GEMM_BLOCKS 276
#define SEL_BLOCKS 256

// ---- device scratch (module globals; no runtime allocation) ----
__device__ float          g_pT[D * C];                   // protos transposed [k][c] (unnormalized)
__device__ float          g_pinv[C];                     // 1/max(||p_c||,eps)
__device__ float          g_sims[B * C * KSPLIT * C];    // partial sims: [listpos][q][C]
__device__ float          g_lossd[B * C];                // per-positive loss / poscnt, dense
__device__ unsigned char  g_mask[B * C];                 // bit0 = rand-negative, bit1 = positive
__device__ float          g_poscnt[B];                   // clip(count,1)
__device__ int            g_cnt[B];                      // positives per batch
__device__ int            g_list[B * 1024];              // column index of each positive, per batch
__device__ unsigned       g_done;                        // select-block completion counter

// packed f32x2 FMA
__device__ __forceinline__ unsigned long long ffma2(unsigned long long a,
                                                    unsigned long long b,
                                                    unsigned long long c) {
    unsigned long long d;
    asm("fma.rn.f32x2 %0, %1, %2, %3;" : "=l"(d) : "l"(a), "l"(b), "l"(c));
    return d;
}

// named barrier for a 256-thread group
__device__ __forceinline__ void gbar(int id) {
    asm volatile("bar.sync %0, 256;" :: "r"(id) : "memory");
}

// ===========================================================================
// Block-wide (1024-thread) radix select: Ksel-th largest among keys (0=excl).
__device__ __forceinline__ void radix_select_desc(
    unsigned key, int Ksel,
    unsigned* hist, unsigned* S, unsigned* wtot,
    unsigned* sh_prefix, unsigned* sh_rem,
    int tid, int lane)
{
    if (tid == 0) { *sh_prefix = 0u; *sh_rem = (unsigned)Ksel; }
    __syncthreads();
#pragma unroll
    for (int byte = 3; byte >= 0; byte--) {
        int shift = byte * 8;
        if (tid < 256) hist[tid] = 0u;
        __syncthreads();
        unsigned pfx = *sh_prefix;
        bool match = (byte == 3) || ((key >> (shift + 8)) == (pfx >> (shift + 8)));
        if (match && key != 0u) atomicAdd(&hist[(key >> shift) & 255u], 1u);
        __syncthreads();
        if (tid < 256) {
            unsigned v = hist[tid];
#pragma unroll
            for (int d = 1; d < 32; d <<= 1) {
                unsigned t2 = __shfl_down_sync(0xFFFFFFFFu, v, d);
                if (lane + d < 32) v += t2;
            }
            S[tid] = v;
            if (lane == 0) wtot[tid >> 5] = v;
        }
        __syncthreads();
        unsigned remloc = *sh_rem;
        if (tid < 256) {
            unsigned ws = 0;
            for (int w = (tid >> 5) + 1; w < 8; w++) ws += wtot[w];
            S[tid] += ws;
        }
        __syncthreads();
        if (tid < 256) {
            unsigned st = S[tid];
            unsigned snext = (tid == 255) ? 0u : S[tid + 1];
            if (st >= remloc && snext < remloc) {
                *sh_prefix = pfx | ((unsigned)tid << shift);
                *sh_rem = remloc - snext;
            }
        }
        __syncthreads();
    }
}

// ===========================================================================
// Group (256-thread, 4 keys/thread) radix select with named barrier `barid`.
__device__ __forceinline__ void radix4(
    const unsigned key[4], int Ksel,
    unsigned* hist, unsigned* S, unsigned* wtot,
    volatile unsigned* sh_prefix, volatile unsigned* sh_rem,
    int gtid, int lane, int wg, int barid)
{
    if (gtid == 0) { *sh_prefix = 0u; *sh_rem = (unsigned)Ksel; }
    gbar(barid);
#pragma unroll
    for (int byte = 3; byte >= 0; byte--) {
        int shift = byte * 8;
        hist[gtid] = 0u;
        gbar(barid);
        unsigned pfx = *sh_prefix;
#pragma unroll
        for (int x = 0; x < 4; x++) {
            bool match = (byte == 3) || ((key[x] >> (shift + 8)) == (pfx >> (shift + 8)));
            if (match && key[x] != 0u) atomicAdd(&hist[(key[x] >> shift) & 255u], 1u);
        }
        gbar(barid);
        unsigned v = hist[gtid];
#pragma unroll
        for (int d = 1; d < 32; d <<= 1) {
            unsigned t2 = __shfl_down_sync(0xFFFFFFFFu, v, d);
            if (lane + d < 32) v += t2;
        }
        if (lane == 0) wtot[wg] = v;
        gbar(barid);
        unsigned remloc = *sh_rem;
        unsigned ws = 0;
        for (int w = wg + 1; w < 8; w++) ws += wtot[w];
        unsigned st = v + ws;            // suffix sum from this bin
        S[gtid] = st;
        gbar(barid);
        unsigned snext = (gtid == 255) ? 0u : S[gtid + 1];
        if (st >= remloc && snext < remloc) {
            *sh_prefix = pfx | ((unsigned)gtid << shift);
            *sh_rem = remloc - snext;
        }
        gbar(barid);
    }
}

// ===========================================================================
// prep (1024 threads/block):
//   [0,768)   : coalesced 32x33 tile transpose p -> g_pT
//   [768,800) : proto row norms -> g_pinv (warp per row)
//   [800,816) : rand-negative + positive mask byte per batch elem
//   [816,832) : rank-based positive compaction (+ g_done reset in blk 816)
__global__ void __launch_bounds__(1024) k_prep(const float* __restrict__ p,
                                               const int* __restrict__ tg,
                                               const float* __restrict__ rs) {
    __shared__ float tile[32][33];
    __shared__ unsigned hist[256];
    __shared__ unsigned S[256];
    __shared__ unsigned wtot[32];
    __shared__ unsigned sh_prefix, sh_rem;
    __shared__ int s_ts;

    int tid = threadIdx.x;
    int lane = tid & 31, wid = tid >> 5;
    int blk = blockIdx.x;

    if (blk < 768) {
        int tx = blk & 31;   // proto-row tile (C dim)
        int ty = blk >> 5;   // feature tile  (D dim)
        tile[wid][lane] = p[(tx * 32 + wid) * D + ty * 32 + lane];
        __syncthreads();
        g_pT[(ty * 32 + wid) * C + tx * 32 + lane] = tile[lane][wid];
        return;
    }
    if (blk < 800) {
        int j = (blk - 768) * 32 + wid;
        const float* pr = p + (size_t)j * D;
        float ss = 0.f;
#pragma unroll
        for (int t = 0; t < 24; t++) { float v = pr[lane + 32 * t]; ss += v * v; }
#pragma unroll
        for (int d = 16; d > 0; d >>= 1) ss += __shfl_xor_sync(0xFFFFFFFFu, ss, d);
        if (lane == 0) g_pinv[j] = 1.f / fmaxf(sqrtf(ss), 1e-12f);
        return;
    }

    // ---- dtype probe on this batch's word window [b*1024, b*1024+1024) ----
    int b = (blk < 816) ? (blk - 800) : (blk - 816);
    int w0 = tg[b * 1024 + tid];                       // word view; in-bounds either dtype
    bool oddnz = ((tid & 1) != 0) && (w0 != 0);
    unsigned ob = __ballot_sync(0xFFFFFFFFu, oddnz);
    if (lane == 0) wtot[wid] = ob ? 1u : 0u;
    __syncthreads();
    if (tid == 0) {
        unsigned fl = 0;
        for (int w = 0; w < 32; w++) fl |= wtot[w];
        s_ts = fl ? 1 : 2;                             // 1=int32, 2=int64
    }
    __syncthreads();
    int ts = s_ts;
    bool posc = (ts == 1) ? (w0 != 0) : (tg[(b * C + tid) * 2] != 0);
    __syncthreads();

    if (blk < 816) {
        // ---- rand-negative membership + mask byte ----
        float r = rs[b * C + tid];
        unsigned key = posc ? 0u : (__float_as_uint(r) + 1u);   // monotone, >0

        radix_select_desc(key, KR, hist, S, wtot, &sh_prefix, &sh_rem, tid, lane);
        unsigned T = sh_prefix;
        unsigned remf = sh_rem;

        // tie resolution by lowest index (matches jax.lax.top_k stability)
        bool eq = (key == T) && (key != 0u);
        unsigned eb = __ballot_sync(0xFFFFFFFFu, eq);
        if (lane == 0) wtot[wid] = (unsigned)__popc(eb);
        __syncthreads();
        unsigned off = 0;
        for (int w = 0; w < wid; w++) off += wtot[w];
        unsigned rank = off + (unsigned)__popc(eb & ((1u << lane) - 1u));
        bool in = (key != 0u) && ((key > T) || (eq && rank < remf));
        g_mask[b * C + tid] = (unsigned char)((posc ? 2 : 0) | (in ? 1 : 0));
    } else {
        // ---- rank-based compaction ----
        unsigned bal = __ballot_sync(0xFFFFFFFFu, posc);
        if (lane == 0) wtot[wid] = (unsigned)__popc(bal);
        __syncthreads();
        unsigned off = 0;
        for (int w = 0; w < wid; w++) off += wtot[w];
        unsigned rank = off + (unsigned)__popc(bal & ((1u << lane) - 1u));
        if (posc) g_list[b * 1024 + rank] = tid;
        if (tid == 0) {
            unsigned cnt = 0;
            for (int w = 0; w < 32; w++) cnt += wtot[w];
            g_cnt[b] = (int)cnt;
            g_poscnt[b] = (float)(cnt > 0 ? cnt : 1u);
            if (b == 0) g_done = 0u;                   // reset tail counter每launch
        }
    }
}

// ===========================================================================
// GEMM: items = (anchor group of GG) x (k-quarter). 256 threads, 4 cols/thread,
// f rows pre-duplicated {v,v} in smem, inner loop = LDS.64-bcast + FFMA2.
__global__ void __launch_bounds__(256) k_gemm(const float* __restrict__ f) {
    __shared__ unsigned long long f2_s[GG][KQ];   // 18,432 B
    __shared__ int s_anchor[GG];
    __shared__ int s_pfx[17];

    int tid = threadIdx.x;
    int wid = tid >> 5, lane = tid & 31;

    if (tid == 0) {
        int acc = 0;
        for (int b = 0; b < B; b++) { s_pfx[b] = acc; acc += g_cnt[b]; }
        s_pfx[16] = acc;
    }
    __syncthreads();
    int npos = s_pfx[16];
    int ng = (npos + GG - 1) / GG;
    int nitems = ng * KSPLIT;

    for (int item = blockIdx.x; item < nitems; item += GEMM_BLOCKS) {
        int grp = item >> 2;
        int quarter = item & 3;
        __syncthreads();   // previous iter's f2_s reads done
        if (tid < GG) {
            int idx = grp * GG + tid;
            int aa = -1;
            if (idx < npos) {
                int bb = 0;
                while (bb < 15 && idx >= s_pfx[bb + 1]) bb++;
                aa = bb * C + g_list[bb * 1024 + (idx - s_pfx[bb])];
            }
            s_anchor[tid] = aa;
        }
        __syncthreads();

        for (int u = wid; u < GG; u += 8) {
            int a = s_anchor[u];
            float vs[24];
            float ss = 0.f;
            if (a >= 0) {
                const float* fr = f + (size_t)a * D;
#pragma unroll
                for (int t = 0; t < 24; t++) {
                    float v = fr[lane + 32 * t];
                    vs[t] = v; ss += v * v;
                }
            } else {
#pragma unroll
                for (int t = 0; t < 24; t++) vs[t] = 0.f;
            }
#pragma unroll
            for (int d = 16; d > 0; d >>= 1) ss += __shfl_xor_sync(0xFFFFFFFFu, ss, d);
            float inv = (1.f / fmaxf(sqrtf(ss), 1e-12f)) * (1.f / TAUF);
#pragma unroll
            for (int t = 0; t < 6; t++) {
                unsigned vb = __float_as_uint(vs[quarter * 6 + t] * inv);
                f2_s[u][lane + 32 * t] = ((unsigned long long)vb << 32) | vb;
            }
        }
        __syncthreads();

        int col = 4 * tid;
        const float* pc = g_pT + (size_t)quarter * KQ * C + col;
        unsigned long long accA[GG], accB[GG];
#pragma unroll
        for (int u = 0; u < GG; u++) { accA[u] = 0ull; accB[u] = 0ull; }

#pragma unroll 4
        for (int k = 0; k < KQ; k++) {
            union { float4 v; unsigned long long ll[2]; } pu;
            pu.v = *(const float4*)(pc + (size_t)k * C);
#pragma unroll
            for (int u = 0; u < GG; u++) {
                unsigned long long fv = f2_s[u][k];
                accA[u] = ffma2(fv, pu.ll[0], accA[u]);
                accB[u] = ffma2(fv, pu.ll[1], accB[u]);
            }
        }

        float4 pinv = *(const float4*)(g_pinv + col);
        int base = grp * GG;
#pragma unroll
        for (int u = 0; u < GG; u++) {
            if (base + u < npos) {
                float2 a2 = *(float2*)&accA[u];
                float2 b2 = *(float2*)&accB[u];
                float4 o;
                o.x = a2.x * pinv.x; o.y = a2.y * pinv.y;
                o.z = b2.x * pinv.z; o.w = b2.y * pinv.w;
                *(float4*)&g_sims[(size_t)(base + u) * (KSPLIT * 1024) +
                                  quarter * 1024 + col] = o;
            }
        }
    }
}

// ===========================================================================
// select+loss+final: 4 independent 256-thread groups per block; per-anchor
// radix select; losses stored pre-divided by poscnt; last block to finish
// performs the flat deterministic sum and writes the scalar output.
__global__ void __launch_bounds__(1024) k_select(float* __restrict__ out) {
    __shared__ unsigned hist[4][256];
    __shared__ unsigned S[4][256];
    __shared__ unsigned wtot[4][8];
    __shared__ unsigned sh_prefix[4], sh_rem[4];
    __shared__ unsigned u_red[4][8];
    __shared__ float    f_red[4][8];
    __shared__ float    s_vT[4], s_possim[4];
    __shared__ int      s_pfx[17];
    __shared__ int      s_last;
    __shared__ float    s_fin[32];

    int tid = threadIdx.x;
    int lane = tid & 31;
    int g = tid >> 8;            // group 0..3
    int gtid = tid & 255;
    int wg = (tid >> 5) & 7;     // warp within group
    int barid = g + 1;

    if (tid == 0) {
        int acc = 0;
        for (int b = 0; b < B; b++) { s_pfx[b] = acc; acc += g_cnt[b]; }
        s_pfx[16] = acc;
    }
    __syncthreads();
    int npos = s_pfx[16];

    for (int i = blockIdx.x * 4 + g; i < npos; i += SEL_BLOCKS * 4) {
        // anchor decode (redundant per thread; no sync needed)
        int bb = 0;
        while (bb < 15 && i >= s_pfx[bb + 1]) bb++;
        int c = g_list[bb * 1024 + (i - s_pfx[bb])];

        // load 4 columns of summed sims (fixed summation order)
        const float* sp = g_sims + (size_t)i * (KSPLIT * 1024) + 4 * gtid;
        float4 q0 = *(const float4*)(sp);
        float4 q1 = *(const float4*)(sp + 1024);
        float4 q2 = *(const float4*)(sp + 2048);
        float4 q3 = *(const float4*)(sp + 3072);
        float sim[4];
        sim[0] = (q0.x + q1.x) + (q2.x + q3.x);
        sim[1] = (q0.y + q1.y) + (q2.y + q3.y);
        sim[2] = (q0.z + q1.z) + (q2.z + q3.z);
        sim[3] = (q0.w + q1.w) + (q2.w + q3.w);

        uchar4 mk4 = *(const uchar4*)(g_mask + bb * C + 4 * gtid);
        unsigned char mk[4] = {mk4.x, mk4.y, mk4.z, mk4.w};

        unsigned key[4];
#pragma unroll
        for (int x = 0; x < 4; x++) {
            unsigned bits = __float_as_uint(sim[x]);
            unsigned flip = bits ^ ((bits & 0x80000000u) ? 0xFFFFFFFFu : 0x80000000u);
            key[x] = (mk[x] & 2) ? 0u : flip;
        }
        if ((c >> 2) == gtid) s_possim[g] = sim[c & 3];

        // max negative key -> m
        unsigned mx = max(max(key[0], key[1]), max(key[2], key[3]));
#pragma unroll
        for (int d = 16; d > 0; d >>= 1) mx = max(mx, __shfl_xor_sync(0xFFFFFFFFu, mx, d));
        if (lane == 0) u_red[g][wg] = mx;
        gbar(barid);
        unsigned maxkey = u_red[g][0];
#pragma unroll
        for (int w = 1; w < 8; w++) maxkey = max(maxkey, u_red[g][w]);
        unsigned mbits = (maxkey & 0x80000000u) ? (maxkey ^ 0x80000000u) : ~maxkey;
        float m = __uint_as_float(mbits);

        radix4(key, KH, hist[g], S[g], wtot[g], &sh_prefix[g], &sh_rem[g],
               gtid, lane, wg, barid);
        unsigned T = sh_prefix[g];
        unsigned remf = sh_rem[g];

        float contrib = 0.f;
#pragma unroll
        for (int x = 0; x < 4; x++) {
            float e = expf(sim[x] - m);
            if (key[x] > T) contrib += e;
            if (key[x] == T && key[x] != 0u) s_vT[g] = sim[x];  // equal keys = equal values
            if (mk[x] & 1) contrib += e;
        }
#pragma unroll
        for (int d = 16; d > 0; d >>= 1) contrib += __shfl_xor_sync(0xFFFFFFFFu, contrib, d);
        if (lane == 0) f_red[g][wg] = contrib;
        gbar(barid);
        if (gtid == 0) {
            float tot = 0.f;
            for (int w = 0; w < 8; w++) tot += f_red[g][w];
            tot += (float)remf * expf(s_vT[g] - m);
            float lse = m + logf(tot);
            float x = lse - s_possim[g];
            float loss = fmaxf(x, 0.f) + log1pf(expf(-fabsf(x)));
            g_lossd[i] = loss / g_poscnt[bb];          // pre-normalized
        }
        gbar(barid);   // close iteration: protect s_possim / s_vT / smem reuse
    }

    // ---- fused final reduction: last block to arrive sums everything ----
    __syncthreads();
    if (tid == 0) {
        __threadfence();
        unsigned r = atomicAdd(&g_done, 1u);
        s_last = (r == SEL_BLOCKS - 1) ? 1 : 0;
    }
    __syncthreads();
    if (s_last) {
        float ps = 0.f;
        for (int j = tid; j < npos; j += 1024) ps += g_lossd[j];
#pragma unroll
        for (int d = 16; d > 0; d >>= 1) ps += __shfl_xor_sync(0xFFFFFFFFu, ps, d);
        if (lane == 0) s_fin[tid >> 5] = ps;
        __syncthreads();
        if (tid < 32) {
            float t = s_fin[tid];
#pragma unroll
            for (int d = 16; d > 0; d >>= 1) t += __shfl_xor_sync(0xFFFFFFFFu, t, d);
            if (tid == 0) out[0] = t / (float)B;
        }
    }
}

// ===========================================================================
extern "C" void kernel_launch(void* const* d_in, const int* in_sizes, int n_in,
                              void* d_out, int out_size) {
    const float* f  = (const float*)d_in[0];   // (B,C,D) fp32
    const float* p  = (const float*)d_in[1];   // (C,D)   fp32
    const int*   tg = (const int*)d_in[2];     // (B,C)   int32 (or int64; self-probed)
    const float* rs = (const float*)d_in[3];   // (B,C)   fp32
    float* out = (float*)d_out;

    k_prep<<<832, 1024>>>(p, tg, rs);
    k_gemm<<<GEMM_BLOCKS, 256>>>(f);
    k_select<<<SEL_BLOCKS, 1024>>>(out);
}